// round 1
// baseline (speedup 1.0000x reference)
#include <cuda_runtime.h>
#include <math.h>

// ---------------- problem constants ----------------
#define BB 4
#define TT 1024
#define DD 1024
#define HH 16
#define LL 6
#define DHH 64
#define OUTD 1024
#define FF (4*DD)
#define BT (BB*TT)           // 4096 rows

// ---------------- scratch (__device__ globals, allocation-free) ----------------
__device__ float g_x[(size_t)BT * DD];          // residual stream
__device__ float g_h[(size_t)BT * DD];          // LN output
__device__ float g_q[(size_t)BT * DD];
__device__ float g_k[(size_t)BT * DD];
__device__ float g_v[(size_t)BT * DD];
__device__ float g_y[(size_t)BT * DD];
__device__ float g_att[(size_t)BB * HH * TT * TT];   // 256 MB
__device__ float g_m[(size_t)BT * FF];               // 64 MB

// ---------------- block reductions ----------------
__device__ __forceinline__ float blockSum(float v) {
    __shared__ float sh[33];
    int lane = threadIdx.x & 31, wid = threadIdx.x >> 5;
    #pragma unroll
    for (int o = 16; o > 0; o >>= 1) v += __shfl_down_sync(0xffffffffu, v, o);
    if (lane == 0) sh[wid] = v;
    __syncthreads();
    v = (threadIdx.x < (blockDim.x >> 5)) ? sh[threadIdx.x] : 0.0f;
    if (wid == 0) {
        #pragma unroll
        for (int o = 16; o > 0; o >>= 1) v += __shfl_down_sync(0xffffffffu, v, o);
    }
    if (threadIdx.x == 0) sh[32] = v;
    __syncthreads();
    float r = sh[32];
    __syncthreads();
    return r;
}

__device__ __forceinline__ float blockMax(float v) {
    __shared__ float sh[33];
    int lane = threadIdx.x & 31, wid = threadIdx.x >> 5;
    #pragma unroll
    for (int o = 16; o > 0; o >>= 1) v = fmaxf(v, __shfl_down_sync(0xffffffffu, v, o));
    if (lane == 0) sh[wid] = v;
    __syncthreads();
    v = (threadIdx.x < (blockDim.x >> 5)) ? sh[threadIdx.x] : -INFINITY;
    if (wid == 0) {
        #pragma unroll
        for (int o = 16; o > 0; o >>= 1) v = fmaxf(v, __shfl_down_sync(0xffffffffu, v, o));
    }
    if (threadIdx.x == 0) sh[32] = v;
    __syncthreads();
    float r = sh[32];
    __syncthreads();
    return r;
}

// ---------------- elementwise: x = seq + pos ----------------
__global__ void add_pos_kernel(const float* __restrict__ seq,
                               const float* __restrict__ pos,
                               float* __restrict__ x, long n) {
    long i = (long)blockIdx.x * blockDim.x + threadIdx.x;
    long stride = (long)gridDim.x * blockDim.x;
    for (; i < n; i += stride)
        x[i] = seq[i] + pos[i & ((long)(TT * DD) - 1)];
}

// ---------------- LayerNorm: one block per row, D=1024, 256 threads ----------------
__global__ void ln_kernel(const float* __restrict__ x,
                          const float* __restrict__ g,
                          const float* __restrict__ b,
                          float* __restrict__ out) {
    long row = blockIdx.x;
    const float* xr = x + row * DD;
    float4 v = *(const float4*)(xr + threadIdx.x * 4);
    float s = v.x + v.y + v.z + v.w;
    float mu = blockSum(s) * (1.0f / DD);
    float dx = v.x - mu, dy = v.y - mu, dz = v.z - mu, dw = v.w - mu;
    float ss = dx * dx + dy * dy + dz * dz + dw * dw;
    float var = blockSum(ss) * (1.0f / DD);
    float rstd = rsqrtf(var + 1e-5f);
    int c = threadIdx.x * 4;
    float4 gg = *(const float4*)(g + c);
    float4 bb2 = *(const float4*)(b + c);
    float4 o;
    o.x = dx * rstd * gg.x + bb2.x;
    o.y = dy * rstd * gg.y + bb2.y;
    o.z = dz * rstd * gg.z + bb2.z;
    o.w = dw * rstd * gg.w + bb2.w;
    *(float4*)(out + row * DD + c) = o;
}

// ---------------- softmax over rows of length T=1024 ----------------
__global__ void softmax_kernel(float* __restrict__ att) {
    long row = blockIdx.x;
    float* r = att + row * (long)TT;
    float4 v = *(const float4*)(r + threadIdx.x * 4);
    float m = fmaxf(fmaxf(v.x, v.y), fmaxf(v.z, v.w));
    float M = blockMax(m);
    float4 e;
    e.x = expf(v.x - M); e.y = expf(v.y - M);
    e.z = expf(v.z - M); e.w = expf(v.w - M);
    float s = e.x + e.y + e.z + e.w;
    float S = blockSum(s);
    float inv = 1.0f / S;
    e.x *= inv; e.y *= inv; e.z *= inv; e.w *= inv;
    *(float4*)(r + threadIdx.x * 4) = e;
}

// ---------------- generic tiled SGEMM ----------------
// C[M,N] = epi(alpha * A[M,K] @ op(B) + bias) (+ res)
// TRB=false: B is [K,N] row-major (NN). TRB=true: B is [N,K] row-major (NT).
// EPI: 0 = alpha only, 1 = +bias, 2 = +bias +res, 3 = +bias then GELU
// Batched via blockIdx.z; batch z -> (bb = z/Hh, hh = z%Hh); per-axis strides.
template <int BM, int BN, int BK, int TM, int TN, bool TRB, int EPI>
__global__ void __launch_bounds__((BM / TM) * (BN / TN))
gemm_kernel(const float* __restrict__ A, const float* __restrict__ Bm,
            const float* __restrict__ bias, const float* __restrict__ res,
            float* __restrict__ C,
            int K, int lda, int ldb, int ldc,
            long sAb, long sAh, long sBb, long sBh, long sCb, long sCh,
            int Hh, float alpha) {
    constexpr int THREADS = (BM / TM) * (BN / TN);
    int z = blockIdx.z;
    int bb = z / Hh, hh = z - bb * Hh;
    A += bb * sAb + hh * sAh;
    Bm += bb * sBb + hh * sBh;
    C += bb * sCb + hh * sCh;
    if (EPI == 2) res += bb * sCb + hh * sCh;

    __shared__ float As[BK][BM];
    __shared__ float Bs[BK][BN];

    int tid = threadIdx.x;
    int m0 = blockIdx.y * BM;
    int n0 = blockIdx.x * BN;
    int tx = tid % (BN / TN);
    int ty = tid / (BN / TN);

    float acc[TM][TN];
    #pragma unroll
    for (int m = 0; m < TM; m++)
        #pragma unroll
        for (int n = 0; n < TN; n++) acc[m][n] = 0.0f;

    for (int k0 = 0; k0 < K; k0 += BK) {
        // load A tile (BM x BK), store transposed
        for (int i = tid; i < BM * BK / 4; i += THREADS) {
            int r = i / (BK / 4);
            int cv = i % (BK / 4);
            float4 a = *(const float4*)(A + (long)(m0 + r) * lda + k0 + cv * 4);
            As[cv * 4 + 0][r] = a.x;
            As[cv * 4 + 1][r] = a.y;
            As[cv * 4 + 2][r] = a.z;
            As[cv * 4 + 3][r] = a.w;
        }
        // load B tile
        if (!TRB) {
            for (int i = tid; i < BK * BN / 4; i += THREADS) {
                int r = i / (BN / 4);
                int cv = i % (BN / 4);
                float4 b4 = *(const float4*)(Bm + (long)(k0 + r) * ldb + n0 + cv * 4);
                *(float4*)(&Bs[r][cv * 4]) = b4;
            }
        } else {
            for (int i = tid; i < BN * BK / 4; i += THREADS) {
                int r = i / (BK / 4);
                int cv = i % (BK / 4);
                float4 b4 = *(const float4*)(Bm + (long)(n0 + r) * ldb + k0 + cv * 4);
                Bs[cv * 4 + 0][r] = b4.x;
                Bs[cv * 4 + 1][r] = b4.y;
                Bs[cv * 4 + 2][r] = b4.z;
                Bs[cv * 4 + 3][r] = b4.w;
            }
        }
        __syncthreads();

        #pragma unroll
        for (int k = 0; k < BK; k++) {
            float ra[TM], rb[TN];
            #pragma unroll
            for (int m = 0; m < TM; m++) ra[m] = As[k][ty * TM + m];
            #pragma unroll
            for (int n = 0; n < TN; n++) rb[n] = Bs[k][tx * TN + n];
            #pragma unroll
            for (int m = 0; m < TM; m++)
                #pragma unroll
                for (int n = 0; n < TN; n++) acc[m][n] += ra[m] * rb[n];
        }
        __syncthreads();
    }

    #pragma unroll
    for (int m = 0; m < TM; m++) {
        int gm = m0 + ty * TM + m;
        #pragma unroll
        for (int n = 0; n < TN; n++) {
            int gn = n0 + tx * TN + n;
            float v = acc[m][n] * alpha;
            if (EPI == 1 || EPI == 2 || EPI == 3) v += bias[gn];
            if (EPI == 3) v = 0.5f * v * (1.0f + erff(v * 0.70710678118654752f));
            if (EPI == 2) v += res[(long)gm * ldc + gn];
            C[(long)gm * ldc + gn] = v;
        }
    }
}

// ---------------- host launch ----------------
extern "C" void kernel_launch(void* const* d_in, const int* in_sizes, int n_in,
                              void* d_out, int out_size) {
    const float* seq    = (const float*)d_in[0];
    const float* pos    = (const float*)d_in[1];
    const float* ln1_g  = (const float*)d_in[2];
    const float* ln1_b  = (const float*)d_in[3];
    const float* wq     = (const float*)d_in[4];
    const float* bq     = (const float*)d_in[5];
    const float* wk     = (const float*)d_in[6];
    const float* bk     = (const float*)d_in[7];
    const float* wv     = (const float*)d_in[8];
    const float* bv     = (const float*)d_in[9];
    const float* wo     = (const float*)d_in[10];
    const float* bo     = (const float*)d_in[11];
    const float* ln2_g  = (const float*)d_in[12];
    const float* ln2_b  = (const float*)d_in[13];
    const float* w1     = (const float*)d_in[14];
    const float* b1     = (const float*)d_in[15];
    const float* w2     = (const float*)d_in[16];
    const float* b2     = (const float*)d_in[17];
    const float* lnf_g  = (const float*)d_in[18];
    const float* lnf_b  = (const float*)d_in[19];
    const float* w_head = (const float*)d_in[20];
    float* out = (float*)d_out;

    float* x = nullptr; float* h = nullptr; float* q = nullptr; float* k = nullptr;
    float* v = nullptr; float* y = nullptr; float* att = nullptr; float* mbuf = nullptr;
    cudaGetSymbolAddress((void**)&x, g_x);
    cudaGetSymbolAddress((void**)&h, g_h);
    cudaGetSymbolAddress((void**)&q, g_q);
    cudaGetSymbolAddress((void**)&k, g_k);
    cudaGetSymbolAddress((void**)&v, g_v);
    cudaGetSymbolAddress((void**)&y, g_y);
    cudaGetSymbolAddress((void**)&att, g_att);
    cudaGetSymbolAddress((void**)&mbuf, g_m);

    const float one = 1.0f;
    const float scale = 1.0f / 8.0f;   // 1/sqrt(64)

    // x = seq + pos
    add_pos_kernel<<<1024, 256>>>(seq, pos, x, (long)BT * DD);

    for (int l = 0; l < LL; l++) {
        const float* Wq = wq + (long)l * DD * DD;
        const float* Wk = wk + (long)l * DD * DD;
        const float* Wv = wv + (long)l * DD * DD;
        const float* Wo = wo + (long)l * DD * DD;
        const float* W1 = w1 + (long)l * DD * FF;
        const float* W2 = w2 + (long)l * FF * DD;
        const float* Bq = bq + (long)l * DD;
        const float* Bk = bk + (long)l * DD;
        const float* Bv = bv + (long)l * DD;
        const float* Bo = bo + (long)l * DD;
        const float* B1 = b1 + (long)l * FF;
        const float* B2 = b2 + (long)l * DD;

        // h = LN1(x)
        ln_kernel<<<BT, 256>>>(x, ln1_g + (long)l * DD, ln1_b + (long)l * DD, h);

        // q/k/v = h @ W + b   [4096,1024,1024] NN, bias epilogue
        {
            dim3 grid(DD / 128, BT / 128, 1);
            gemm_kernel<128, 128, 8, 8, 8, false, 1><<<grid, 256>>>(
                h, Wq, Bq, nullptr, q, DD, DD, DD, DD, 0, 0, 0, 0, 0, 0, 1, one);
            gemm_kernel<128, 128, 8, 8, 8, false, 1><<<grid, 256>>>(
                h, Wk, Bk, nullptr, k, DD, DD, DD, DD, 0, 0, 0, 0, 0, 0, 1, one);
            gemm_kernel<128, 128, 8, 8, 8, false, 1><<<grid, 256>>>(
                h, Wv, Bv, nullptr, v, DD, DD, DD, DD, 0, 0, 0, 0, 0, 0, 1, one);
        }

        // att[b,h,t,s] = scale * Q Kᵀ : NT batched, 64 batches of [1024,1024,64]
        {
            dim3 grid(TT / 128, TT / 128, BB * HH);
            gemm_kernel<128, 128, 8, 8, 8, true, 0><<<grid, 256>>>(
                q, k, nullptr, nullptr, att, DHH, DD, DD, TT,
                (long)TT * DD, (long)DHH,            // A strides (b, h)
                (long)TT * DD, (long)DHH,            // B strides (b, h)
                (long)HH * TT * TT, (long)TT * TT,   // C strides (b, h)
                HH, scale);
        }

        // softmax rows
        softmax_kernel<<<BB * HH * TT, 256>>>(att);

        // y = att @ V : NN batched [1024, 64, 1024]
        {
            dim3 grid(DHH / 64, TT / 128, BB * HH);
            gemm_kernel<128, 64, 8, 8, 4, false, 0><<<grid, 256>>>(
                att, v, nullptr, nullptr, y, TT, TT, DD, DD,
                (long)HH * TT * TT, (long)TT * TT,
                (long)TT * DD, (long)DHH,
                (long)TT * DD, (long)DHH,
                HH, one);
        }

        // x = x + y @ Wo + bo  (bias + residual)
        {
            dim3 grid(DD / 128, BT / 128, 1);
            gemm_kernel<128, 128, 8, 8, 8, false, 2><<<grid, 256>>>(
                y, Wo, Bo, x, x, DD, DD, DD, DD, 0, 0, 0, 0, 0, 0, 1, one);
        }

        // h = LN2(x)
        ln_kernel<<<BT, 256>>>(x, ln2_g + (long)l * DD, ln2_b + (long)l * DD, h);

        // m = gelu(h @ W1 + b1)  [4096, 4096, 1024]
        {
            dim3 grid(FF / 128, BT / 128, 1);
            gemm_kernel<128, 128, 8, 8, 8, false, 3><<<grid, 256>>>(
                h, W1, B1, nullptr, mbuf, DD, DD, FF, FF, 0, 0, 0, 0, 0, 0, 1, one);
        }

        // x = x + m @ W2 + b2  [4096, 1024, 4096]
        {
            dim3 grid(DD / 128, BT / 128, 1);
            gemm_kernel<128, 128, 8, 8, 8, false, 2><<<grid, 256>>>(
                mbuf, W2, B2, x, x, FF, FF, DD, DD, 0, 0, 0, 0, 0, 0, 1, one);
        }
    }

    // h = LNf(x)
    ln_kernel<<<BT, 256>>>(x, lnf_g, lnf_b, h);

    // out = h @ w_head  [4096, 1024, 1024]
    {
        dim3 grid(OUTD / 128, BT / 128, 1);
        gemm_kernel<128, 128, 8, 8, 8, false, 0><<<grid, 256>>>(
            h, w_head, nullptr, nullptr, out, DD, DD, OUTD, OUTD,
            0, 0, 0, 0, 0, 0, 1, one);
    }
}

// round 3
// speedup vs baseline: 2.6730x; 2.6730x over previous
#include <cuda_runtime.h>
#include <cuda_bf16.h>
#include <math.h>
#include <stdint.h>

#define NBAT 4
#define TSEQ 1024
#define DMOD 1024
#define NHEAD 16
#define NLAY 6
#define DHEAD 64
#define FDIM 4096
#define NROWS 4096

typedef __nv_bfloat16 bf16;
typedef __nv_bfloat162 bf162;

// ---------------- device scratch (allocation-free) ----------------
__device__ float g_x[(size_t)NROWS * DMOD];
__device__ float g_v[(size_t)NROWS * DMOD];
__device__ float g_att[(size_t)NBAT * NHEAD * TSEQ * TSEQ];

__device__ bf16 g_h_h[(size_t)NROWS * DMOD];
__device__ bf16 g_h_l[(size_t)NROWS * DMOD];
__device__ bf16 g_q_h[(size_t)NROWS * DMOD];
__device__ bf16 g_q_l[(size_t)NROWS * DMOD];
__device__ bf16 g_k_h[(size_t)NROWS * DMOD];
__device__ bf16 g_k_l[(size_t)NROWS * DMOD];
__device__ bf16 g_vt_h[(size_t)NROWS * DMOD];
__device__ bf16 g_vt_l[(size_t)NROWS * DMOD];
__device__ bf16 g_y_h[(size_t)NROWS * DMOD];
__device__ bf16 g_y_l[(size_t)NROWS * DMOD];
__device__ bf16 g_att_h[(size_t)NBAT * NHEAD * TSEQ * TSEQ];
__device__ bf16 g_att_l[(size_t)NBAT * NHEAD * TSEQ * TSEQ];
__device__ bf16 g_m_h[(size_t)NROWS * FDIM];
__device__ bf16 g_m_l[(size_t)NROWS * FDIM];

// transposed+split weights: [N, K] layout
__device__ bf16 g_wq_h[(size_t)NLAY * DMOD * DMOD];
__device__ bf16 g_wq_l[(size_t)NLAY * DMOD * DMOD];
__device__ bf16 g_wk_h[(size_t)NLAY * DMOD * DMOD];
__device__ bf16 g_wk_l[(size_t)NLAY * DMOD * DMOD];
__device__ bf16 g_wv_h[(size_t)NLAY * DMOD * DMOD];
__device__ bf16 g_wv_l[(size_t)NLAY * DMOD * DMOD];
__device__ bf16 g_wo_h[(size_t)NLAY * DMOD * DMOD];
__device__ bf16 g_wo_l[(size_t)NLAY * DMOD * DMOD];
__device__ bf16 g_w1_h[(size_t)NLAY * FDIM * DMOD];
__device__ bf16 g_w1_l[(size_t)NLAY * FDIM * DMOD];
__device__ bf16 g_w2_h[(size_t)NLAY * DMOD * FDIM];
__device__ bf16 g_w2_l[(size_t)NLAY * DMOD * FDIM];
__device__ bf16 g_wh_h[(size_t)DMOD * DMOD];
__device__ bf16 g_wh_l[(size_t)DMOD * DMOD];

// ---------------- PTX helpers ----------------
__device__ __forceinline__ uint32_t smem_u32(const void* p) {
    return (uint32_t)__cvta_generic_to_shared(p);
}

__device__ __forceinline__ void cpa16(uint32_t s, const void* g) {
    asm volatile("cp.async.cg.shared.global [%0], [%1], 16;" :: "r"(s), "l"(g) : "memory");
}
__device__ __forceinline__ void cp_commit() {
    asm volatile("cp.async.commit_group;" ::: "memory");
}
template <int N>
__device__ __forceinline__ void cp_wait() {
    asm volatile("cp.async.wait_group %0;" :: "n"(N) : "memory");
}

__device__ __forceinline__ void ldsm4(uint32_t (&r)[4], uint32_t a) {
    asm volatile("ldmatrix.sync.aligned.m8n8.x4.shared.b16 {%0,%1,%2,%3}, [%4];"
                 : "=r"(r[0]), "=r"(r[1]), "=r"(r[2]), "=r"(r[3]) : "r"(a));
}

__device__ __forceinline__ void mma16816(float (&d)[4], const uint32_t (&a)[4],
                                         uint32_t b0, uint32_t b1) {
    asm volatile(
        "mma.sync.aligned.m16n8k16.row.col.f32.bf16.bf16.f32 "
        "{%0,%1,%2,%3}, {%4,%5,%6,%7}, {%8,%9}, {%0,%1,%2,%3};"
        : "+f"(d[0]), "+f"(d[1]), "+f"(d[2]), "+f"(d[3])
        : "r"(a[0]), "r"(a[1]), "r"(a[2]), "r"(a[3]), "r"(b0), "r"(b1));
}

// pack two floats into bf16 hi pair + lo pair (2-term split)
__device__ __forceinline__ void packsplit2(float a, float b, uint32_t& hp, uint32_t& lp) {
    bf16 ha = __float2bfloat16(a);
    bf16 hb = __float2bfloat16(b);
    bf16 la = __float2bfloat16(a - __bfloat162float(ha));
    bf16 lb = __float2bfloat16(b - __bfloat162float(hb));
    bf162 h2; h2.x = ha; h2.y = hb;
    bf162 l2; l2.x = la; l2.y = lb;
    hp = *(uint32_t*)&h2;
    lp = *(uint32_t*)&l2;
}

// ---------------- block reductions ----------------
__device__ __forceinline__ float blockSum(float v) {
    __shared__ float sh[33];
    int lane = threadIdx.x & 31, wid = threadIdx.x >> 5;
    #pragma unroll
    for (int o = 16; o > 0; o >>= 1) v += __shfl_down_sync(0xffffffffu, v, o);
    if (lane == 0) sh[wid] = v;
    __syncthreads();
    v = (threadIdx.x < (blockDim.x >> 5)) ? sh[threadIdx.x] : 0.0f;
    if (wid == 0) {
        #pragma unroll
        for (int o = 16; o > 0; o >>= 1) v += __shfl_down_sync(0xffffffffu, v, o);
    }
    if (threadIdx.x == 0) sh[32] = v;
    __syncthreads();
    float r = sh[32];
    __syncthreads();
    return r;
}

__device__ __forceinline__ float blockMax(float v) {
    __shared__ float sh[33];
    int lane = threadIdx.x & 31, wid = threadIdx.x >> 5;
    #pragma unroll
    for (int o = 16; o > 0; o >>= 1) v = fmaxf(v, __shfl_down_sync(0xffffffffu, v, o));
    if (lane == 0) sh[wid] = v;
    __syncthreads();
    v = (threadIdx.x < (blockDim.x >> 5)) ? sh[threadIdx.x] : -INFINITY;
    if (wid == 0) {
        #pragma unroll
        for (int o = 16; o > 0; o >>= 1) v = fmaxf(v, __shfl_down_sync(0xffffffffu, v, o));
    }
    if (threadIdx.x == 0) sh[32] = v;
    __syncthreads();
    float r = sh[32];
    __syncthreads();
    return r;
}

// ---------------- elementwise: x = seq + pos ----------------
__global__ void add_pos_kernel(const float* __restrict__ seq,
                               const float* __restrict__ pos,
                               float* __restrict__ x, long n) {
    long i = (long)blockIdx.x * blockDim.x + threadIdx.x;
    long stride = (long)gridDim.x * blockDim.x;
    for (; i < n; i += stride)
        x[i] = seq[i] + pos[i & ((long)(TSEQ * DMOD) - 1)];
}

// ---------------- LayerNorm -> bf16 hi/lo ----------------
__global__ void ln_kernel(const float* __restrict__ x,
                          const float* __restrict__ g,
                          const float* __restrict__ b,
                          bf16* __restrict__ oh, bf16* __restrict__ ol) {
    long row = blockIdx.x;
    const float* xr = x + row * DMOD;
    float4 v = *(const float4*)(xr + threadIdx.x * 4);
    float s = v.x + v.y + v.z + v.w;
    float mu = blockSum(s) * (1.0f / DMOD);
    float dx = v.x - mu, dy = v.y - mu, dz = v.z - mu, dw = v.w - mu;
    float ss = dx * dx + dy * dy + dz * dz + dw * dw;
    float var = blockSum(ss) * (1.0f / DMOD);
    float rstd = rsqrtf(var + 1e-5f);
    int c = threadIdx.x * 4;
    float4 gg = *(const float4*)(g + c);
    float4 bb2 = *(const float4*)(b + c);
    float o0 = dx * rstd * gg.x + bb2.x;
    float o1 = dy * rstd * gg.y + bb2.y;
    float o2 = dz * rstd * gg.z + bb2.z;
    float o3 = dw * rstd * gg.w + bb2.w;
    uint32_t h0, l0, h1, l1;
    packsplit2(o0, o1, h0, l0);
    packsplit2(o2, o3, h1, l1);
    long base = row * DMOD + c;
    *(uint32_t*)(oh + base) = h0;
    *(uint32_t*)(oh + base + 2) = h1;
    *(uint32_t*)(ol + base) = l0;
    *(uint32_t*)(ol + base + 2) = l1;
}

// ---------------- softmax (fp32 in) -> bf16 hi/lo ----------------
__global__ void softmax_kernel(const float* __restrict__ att,
                               bf16* __restrict__ oh, bf16* __restrict__ ol) {
    long row = blockIdx.x;
    const float* r = att + row * (long)TSEQ;
    float4 v = *(const float4*)(r + threadIdx.x * 4);
    float m = fmaxf(fmaxf(v.x, v.y), fmaxf(v.z, v.w));
    float M = blockMax(m);
    float e0 = expf(v.x - M), e1 = expf(v.y - M);
    float e2 = expf(v.z - M), e3 = expf(v.w - M);
    float S = blockSum(e0 + e1 + e2 + e3);
    float inv = 1.0f / S;
    e0 *= inv; e1 *= inv; e2 *= inv; e3 *= inv;
    uint32_t h0, l0, h1, l1;
    packsplit2(e0, e1, h0, l0);
    packsplit2(e2, e3, h1, l1);
    long base = row * (long)TSEQ + threadIdx.x * 4;
    *(uint32_t*)(oh + base) = h0;
    *(uint32_t*)(oh + base + 2) = h1;
    *(uint32_t*)(ol + base) = l0;
    *(uint32_t*)(ol + base + 2) = l1;
}

// ---------------- transpose + bf16 split: W[K,N] -> Wt_hi/lo[N,K] ----------------
__global__ void tsplit_kernel(const float* __restrict__ W, bf16* __restrict__ hi,
                              bf16* __restrict__ lo, int Kd, int Nd) {
    __shared__ float sh[32][33];
    long zoff = (long)blockIdx.z * Kd * Nd;
    W += zoff; hi += zoff; lo += zoff;
    int n0 = blockIdx.x * 32, k0 = blockIdx.y * 32;
    int tx = threadIdx.x, ty = threadIdx.y;   // 32 x 8
    #pragma unroll
    for (int i = 0; i < 32; i += 8)
        sh[ty + i][tx] = W[(long)(k0 + ty + i) * Nd + n0 + tx];
    __syncthreads();
    #pragma unroll
    for (int i = 0; i < 32; i += 8) {
        float v = sh[tx][ty + i];
        long o = (long)(n0 + ty + i) * Kd + k0 + tx;
        bf16 h2 = __float2bfloat16(v);
        hi[o] = h2;
        lo[o] = __float2bfloat16(v - __bfloat162float(h2));
    }
}

// ---------------- mma.sync GEMM ----------------
// C[M,N] = epi( alpha * (Ahi+Alo)[M,K] @ (Bhi+Blo)[N,K]^T )
// BM=128, BK=32, BN template. 8 warps. hi/lo: 3 MMAs per tile product.
// EPI: 0 = Cf=alpha*acc ; 1 = hi/lo(acc+bias) ; 3 = Cf=acc+bias+res ;
//      4 = hi/lo(gelu(acc+bias)) ; 5 = hi/lo(acc) ; 6 = Cf=acc+bias
template <int BN, int WARPS_M, int EPI>
__global__ void __launch_bounds__(256)
gemm_mma(const bf16* __restrict__ Ah, const bf16* __restrict__ Al,
         const bf16* __restrict__ Bh, const bf16* __restrict__ Bl,
         const float* __restrict__ bias, const float* __restrict__ res,
         float* __restrict__ Cf, bf16* __restrict__ Ch, bf16* __restrict__ Cl,
         int K, int lda, int ldb, int ldc,
         long sAb, long sAh2, long sBb, long sBh2, long sCb, long sCh2, int Hh,
         float alpha) {
    constexpr int WARPS_N = 8 / WARPS_M;
    constexpr int WM = 128 / WARPS_M;
    constexpr int WN = BN / WARPS_N;
    constexpr int MT = WM / 16;
    constexpr int NT8 = WN / 8;
    constexpr int NPAIR = WN / 16;
    constexpr int ASZ = 128 * 80;          // 128 rows x 80B
    constexpr int BSZ = BN * 80;
    constexpr int STG = 2 * ASZ + 2 * BSZ; // Ah, Al, Bh, Bl

    extern __shared__ char smem[];
    const uint32_t sbase = smem_u32(smem);

    const int tid = threadIdx.x;
    const int wid = tid >> 5;
    const int lane = tid & 31;
    const int wm = wid % WARPS_M;
    const int wn = wid / WARPS_M;

    int z = blockIdx.z;
    int bb = z / Hh, hh = z - bb * Hh;
    Ah += bb * sAb + hh * sAh2;
    Al += bb * sAb + hh * sAh2;
    Bh += bb * sBb + hh * sBh2;
    Bl += bb * sBb + hh * sBh2;
    const long coff = bb * sCb + hh * sCh2;
    const int m0 = blockIdx.y * 128;
    const int n0 = blockIdx.x * BN;

    float acc[MT][NT8][4];
    #pragma unroll
    for (int i = 0; i < MT; i++)
        #pragma unroll
        for (int j = 0; j < NT8; j++)
            #pragma unroll
            for (int q = 0; q < 4; q++) acc[i][j][q] = 0.0f;

    const int nC = K >> 5;

    // ---- chunk loader ----
    auto load_chunk = [&](int buf, int kc) {
        uint32_t sA_h = sbase + buf * STG;
        uint32_t sA_l = sA_h + ASZ;
        uint32_t sB_h = sA_l + ASZ;
        uint32_t sB_l = sB_h + BSZ;
        #pragma unroll
        for (int i = tid; i < 512; i += 256) {
            int r = i >> 2, c = i & 3;
            const bf16* gh = Ah + (long)(m0 + r) * lda + kc + c * 8;
            const bf16* gl = Al + (long)(m0 + r) * lda + kc + c * 8;
            cpa16(sA_h + r * 80 + c * 16, gh);
            cpa16(sA_l + r * 80 + c * 16, gl);
        }
        #pragma unroll
        for (int i = tid; i < BN * 4; i += 256) {
            int r = i >> 2, c = i & 3;
            const bf16* gh = Bh + (long)(n0 + r) * ldb + kc + c * 8;
            const bf16* gl = Bl + (long)(n0 + r) * ldb + kc + c * 8;
            cpa16(sB_h + r * 80 + c * 16, gh);
            cpa16(sB_l + r * 80 + c * 16, gl);
        }
        cp_commit();
    };

    load_chunk(0, 0);

    for (int ic = 0; ic < nC; ic++) {
        bool more = (ic + 1) < nC;
        if (more) load_chunk((ic + 1) & 1, (ic + 1) << 5);
        if (more) cp_wait<1>(); else cp_wait<0>();
        __syncthreads();

        const int buf = ic & 1;
        uint32_t sA_h = sbase + buf * STG;
        uint32_t sA_l = sA_h + ASZ;
        uint32_t sB_h = sA_l + ASZ;
        uint32_t sB_l = sB_h + BSZ;

        #pragma unroll
        for (int ks = 0; ks < 2; ks++) {
            const int kb = ks * 32;
            uint32_t a_h[MT][4], a_l[MT][4];
            uint32_t b_h[NPAIR][4], b_l[NPAIR][4];
            // A frags
            const uint32_t arow = wm * WM + (lane & 15);
            const uint32_t abyte = ((lane >> 4) << 4) + kb;
            #pragma unroll
            for (int mt = 0; mt < MT; mt++) {
                uint32_t ad = (arow + mt * 16) * 80 + abyte;
                ldsm4(a_h[mt], sA_h + ad);
                ldsm4(a_l[mt], sA_l + ad);
            }
            // B frags (two n8 tiles per x4)
            const uint32_t brow0 = wn * WN + ((lane >> 4) << 3) + (lane & 7);
            const uint32_t bbyte = (((lane >> 3) & 1) << 4) + kb;
            #pragma unroll
            for (int p = 0; p < NPAIR; p++) {
                uint32_t bd = (brow0 + p * 16) * 80 + bbyte;
                ldsm4(b_h[p], sB_h + bd);
                ldsm4(b_l[p], sB_l + bd);
            }
            // MMAs: hi*hi, hi*lo, lo*hi
            #pragma unroll
            for (int mt = 0; mt < MT; mt++) {
                #pragma unroll
                for (int nt = 0; nt < NT8; nt++) {
                    int p = nt >> 1, ix = (nt & 1) * 2;
                    mma16816(acc[mt][nt], a_h[mt], b_h[p][ix], b_h[p][ix + 1]);
                    mma16816(acc[mt][nt], a_h[mt], b_l[p][ix], b_l[p][ix + 1]);
                    mma16816(acc[mt][nt], a_l[mt], b_h[p][ix], b_h[p][ix + 1]);
                }
            }
        }
        __syncthreads();
    }

    // ---- epilogue ----
    const int r0 = m0 + wm * WM + (lane >> 2);
    const int c0 = n0 + wn * WN + (lane & 3) * 2;
    #pragma unroll
    for (int mt = 0; mt < MT; mt++) {
        #pragma unroll
        for (int half = 0; half < 2; half++) {
            const long gm = r0 + mt * 16 + half * 8;
            #pragma unroll
            for (int nt = 0; nt < NT8; nt++) {
                const int gc = c0 + nt * 8;
                float v0 = acc[mt][nt][half * 2 + 0];
                float v1 = acc[mt][nt][half * 2 + 1];
                if (EPI == 1 || EPI == 3 || EPI == 4 || EPI == 6) {
                    v0 += bias[gc]; v1 += bias[gc + 1];
                }
                if (EPI == 0) { v0 *= alpha; v1 *= alpha; }
                if (EPI == 4) {
                    v0 = 0.5f * v0 * (1.0f + erff(v0 * 0.70710678118654752f));
                    v1 = 0.5f * v1 * (1.0f + erff(v1 * 0.70710678118654752f));
                }
                if (EPI == 3) {
                    float2 r2 = *(const float2*)(res + coff + gm * ldc + gc);
                    v0 += r2.x; v1 += r2.y;
                }
                if (EPI == 0 || EPI == 3 || EPI == 6) {
                    *(float2*)(Cf + coff + gm * ldc + gc) = make_float2(v0, v1);
                } else {
                    uint32_t hp, lp;
                    packsplit2(v0, v1, hp, lp);
                    *(uint32_t*)(Ch + coff + gm * ldc + gc) = hp;
                    *(uint32_t*)(Cl + coff + gm * ldc + gc) = lp;
                }
            }
        }
    }
}

// ---------------- host launch ----------------
extern "C" void kernel_launch(void* const* d_in, const int* in_sizes, int n_in,
                              void* d_out, int out_size) {
    const float* seq    = (const float*)d_in[0];
    const float* pos    = (const float*)d_in[1];
    const float* ln1_g  = (const float*)d_in[2];
    const float* ln1_b  = (const float*)d_in[3];
    const float* wq     = (const float*)d_in[4];
    const float* bq     = (const float*)d_in[5];
    const float* wk     = (const float*)d_in[6];
    const float* bk     = (const float*)d_in[7];
    const float* wv     = (const float*)d_in[8];
    const float* bv     = (const float*)d_in[9];
    const float* wo     = (const float*)d_in[10];
    const float* bo     = (const float*)d_in[11];
    const float* ln2_g  = (const float*)d_in[12];
    const float* ln2_b  = (const float*)d_in[13];
    const float* w1     = (const float*)d_in[14];
    const float* b1     = (const float*)d_in[15];
    const float* w2     = (const float*)d_in[16];
    const float* b2     = (const float*)d_in[17];
    const float* lnf_g  = (const float*)d_in[18];
    const float* lnf_b  = (const float*)d_in[19];
    const float* w_head = (const float*)d_in[20];
    float* out = (float*)d_out;

    float *x, *vbuf, *att;
    bf16 *h_h, *h_l, *q_h, *q_l, *k_h, *k_l, *vt_h, *vt_l, *y_h, *y_l;
    bf16 *att_h, *att_l, *m_h, *m_l;
    bf16 *wqt_h, *wqt_l, *wkt_h, *wkt_l, *wvt_h, *wvt_l, *wot_h, *wot_l;
    bf16 *w1t_h, *w1t_l, *w2t_h, *w2t_l, *wht_h, *wht_l;
    cudaGetSymbolAddress((void**)&x, g_x);
    cudaGetSymbolAddress((void**)&vbuf, g_v);
    cudaGetSymbolAddress((void**)&att, g_att);
    cudaGetSymbolAddress((void**)&h_h, g_h_h);
    cudaGetSymbolAddress((void**)&h_l, g_h_l);
    cudaGetSymbolAddress((void**)&q_h, g_q_h);
    cudaGetSymbolAddress((void**)&q_l, g_q_l);
    cudaGetSymbolAddress((void**)&k_h, g_k_h);
    cudaGetSymbolAddress((void**)&k_l, g_k_l);
    cudaGetSymbolAddress((void**)&vt_h, g_vt_h);
    cudaGetSymbolAddress((void**)&vt_l, g_vt_l);
    cudaGetSymbolAddress((void**)&y_h, g_y_h);
    cudaGetSymbolAddress((void**)&y_l, g_y_l);
    cudaGetSymbolAddress((void**)&att_h, g_att_h);
    cudaGetSymbolAddress((void**)&att_l, g_att_l);
    cudaGetSymbolAddress((void**)&m_h, g_m_h);
    cudaGetSymbolAddress((void**)&m_l, g_m_l);
    cudaGetSymbolAddress((void**)&wqt_h, g_wq_h);
    cudaGetSymbolAddress((void**)&wqt_l, g_wq_l);
    cudaGetSymbolAddress((void**)&wkt_h, g_wk_h);
    cudaGetSymbolAddress((void**)&wkt_l, g_wk_l);
    cudaGetSymbolAddress((void**)&wvt_h, g_wv_h);
    cudaGetSymbolAddress((void**)&wvt_l, g_wv_l);
    cudaGetSymbolAddress((void**)&wot_h, g_wo_h);
    cudaGetSymbolAddress((void**)&wot_l, g_wo_l);
    cudaGetSymbolAddress((void**)&w1t_h, g_w1_h);
    cudaGetSymbolAddress((void**)&w1t_l, g_w1_l);
    cudaGetSymbolAddress((void**)&w2t_h, g_w2_h);
    cudaGetSymbolAddress((void**)&w2t_l, g_w2_l);
    cudaGetSymbolAddress((void**)&wht_h, g_wh_h);
    cudaGetSymbolAddress((void**)&wht_l, g_wh_l);

    constexpr int SM128 = 2 * (2 * 128 * 80 + 2 * 128 * 80);  // 81920
    constexpr int SM64  = 2 * (2 * 128 * 80 + 2 * 64 * 80);   // 61440
    cudaFuncSetAttribute(gemm_mma<128, 2, 0>, cudaFuncAttributeMaxDynamicSharedMemorySize, SM128);
    cudaFuncSetAttribute(gemm_mma<128, 2, 1>, cudaFuncAttributeMaxDynamicSharedMemorySize, SM128);
    cudaFuncSetAttribute(gemm_mma<128, 2, 3>, cudaFuncAttributeMaxDynamicSharedMemorySize, SM128);
    cudaFuncSetAttribute(gemm_mma<128, 2, 4>, cudaFuncAttributeMaxDynamicSharedMemorySize, SM128);
    cudaFuncSetAttribute(gemm_mma<128, 2, 6>, cudaFuncAttributeMaxDynamicSharedMemorySize, SM128);
    cudaFuncSetAttribute(gemm_mma<64, 4, 5>,  cudaFuncAttributeMaxDynamicSharedMemorySize, SM64);

    dim3 tb(32, 8);
    tsplit_kernel<<<dim3(32, 32, NLAY), tb>>>(wq, wqt_h, wqt_l, DMOD, DMOD);
    tsplit_kernel<<<dim3(32, 32, NLAY), tb>>>(wk, wkt_h, wkt_l, DMOD, DMOD);
    tsplit_kernel<<<dim3(32, 32, NLAY), tb>>>(wv, wvt_h, wvt_l, DMOD, DMOD);
    tsplit_kernel<<<dim3(32, 32, NLAY), tb>>>(wo, wot_h, wot_l, DMOD, DMOD);
    tsplit_kernel<<<dim3(128, 32, NLAY), tb>>>(w1, w1t_h, w1t_l, DMOD, FDIM);
    tsplit_kernel<<<dim3(32, 128, NLAY), tb>>>(w2, w2t_h, w2t_l, FDIM, DMOD);
    tsplit_kernel<<<dim3(32, 32, 1), tb>>>(w_head, wht_h, wht_l, DMOD, DMOD);

    add_pos_kernel<<<1024, 256>>>(seq, pos, x, (long)NROWS * DMOD);

    for (int l = 0; l < NLAY; l++) {
        const long wo2 = (long)l * DMOD * DMOD;
        const long wf  = (long)l * FDIM * DMOD;
        const float* Bq = bq + (long)l * DMOD;
        const float* Bk = bk + (long)l * DMOD;
        const float* Bv = bv + (long)l * DMOD;
        const float* Bo = bo + (long)l * DMOD;
        const float* B1 = b1 + (long)l * FDIM;
        const float* B2 = b2 + (long)l * DMOD;

        ln_kernel<<<NROWS, 256>>>(x, ln1_g + (long)l * DMOD, ln1_b + (long)l * DMOD, h_h, h_l);

        gemm_mma<128, 2, 1><<<dim3(8, 32, 1), 256, SM128>>>(
            h_h, h_l, wqt_h + wo2, wqt_l + wo2, Bq, nullptr, nullptr, q_h, q_l,
            DMOD, DMOD, DMOD, DMOD, 0, 0, 0, 0, 0, 0, 1, 1.0f);
        gemm_mma<128, 2, 1><<<dim3(8, 32, 1), 256, SM128>>>(
            h_h, h_l, wkt_h + wo2, wkt_l + wo2, Bk, nullptr, nullptr, k_h, k_l,
            DMOD, DMOD, DMOD, DMOD, 0, 0, 0, 0, 0, 0, 1, 1.0f);
        gemm_mma<128, 2, 6><<<dim3(8, 32, 1), 256, SM128>>>(
            h_h, h_l, wvt_h + wo2, wvt_l + wo2, Bv, nullptr, vbuf, nullptr, nullptr,
            DMOD, DMOD, DMOD, DMOD, 0, 0, 0, 0, 0, 0, 1, 1.0f);
        // vT[b, d, t] = v[b*T+t, d]
        tsplit_kernel<<<dim3(32, 32, NBAT), tb>>>(vbuf, vt_h, vt_l, TSEQ, DMOD);

        // att = scale * q k^T  (batched over b,h)
        gemm_mma<128, 2, 0><<<dim3(8, 8, NBAT * NHEAD), 256, SM128>>>(
            q_h, q_l, k_h, k_l, nullptr, nullptr, att, nullptr, nullptr,
            DHEAD, DMOD, DMOD, TSEQ,
            (long)TSEQ * DMOD, (long)DHEAD,
            (long)TSEQ * DMOD, (long)DHEAD,
            (long)NHEAD * TSEQ * TSEQ, (long)TSEQ * TSEQ,
            NHEAD, 0.125f);

        softmax_kernel<<<NBAT * NHEAD * TSEQ, 256>>>(att, att_h, att_l);

        // y = att @ v  (batched, N=64)
        gemm_mma<64, 4, 5><<<dim3(1, 8, NBAT * NHEAD), 256, SM64>>>(
            att_h, att_l, vt_h, vt_l, nullptr, nullptr, nullptr, y_h, y_l,
            TSEQ, TSEQ, TSEQ, DMOD,
            (long)NHEAD * TSEQ * TSEQ, (long)TSEQ * TSEQ,
            (long)DMOD * TSEQ, (long)DHEAD * TSEQ,
            (long)TSEQ * DMOD, (long)DHEAD,
            NHEAD, 1.0f);

        // x = x + y @ Wo + bo
        gemm_mma<128, 2, 3><<<dim3(8, 32, 1), 256, SM128>>>(
            y_h, y_l, wot_h + wo2, wot_l + wo2, Bo, x, x, nullptr, nullptr,
            DMOD, DMOD, DMOD, DMOD, 0, 0, 0, 0, 0, 0, 1, 1.0f);

        ln_kernel<<<NROWS, 256>>>(x, ln2_g + (long)l * DMOD, ln2_b + (long)l * DMOD, h_h, h_l);

        // m = gelu(h @ W1 + b1)
        gemm_mma<128, 2, 4><<<dim3(32, 32, 1), 256, SM128>>>(
            h_h, h_l, w1t_h + wf, w1t_l + wf, B1, nullptr, nullptr, m_h, m_l,
            DMOD, DMOD, DMOD, FDIM, 0, 0, 0, 0, 0, 0, 1, 1.0f);

        // x = x + m @ W2 + b2
        gemm_mma<128, 2, 3><<<dim3(8, 32, 1), 256, SM128>>>(
            m_h, m_l, w2t_h + wf, w2t_l + wf, B2, x, x, nullptr, nullptr,
            FDIM, FDIM, FDIM, DMOD, 0, 0, 0, 0, 0, 0, 1, 1.0f);
    }

    ln_kernel<<<NROWS, 256>>>(x, lnf_g, lnf_b, h_h, h_l);

    gemm_mma<128, 2, 0><<<dim3(8, 32, 1), 256, SM128>>>(
        h_h, h_l, wht_h, wht_l, nullptr, nullptr, out, nullptr, nullptr,
        DMOD, DMOD, DMOD, DMOD, 0, 0, 0, 0, 0, 0, 1, 1.0f);
}